// round 3
// baseline (speedup 1.0000x reference)
#include <cuda_runtime.h>
#include <math.h>

#define HW   (128*128)
#define CHW  (16*HW)
typedef unsigned long long ull;

// ---------------- scratch ----------------
__device__ float g_b1[7*CHW];    // conv1 out (3) / conv3 out (7)
__device__ float g_b2[5*CHW];    // conv2 out (5) -- kept for final skip recompute
__device__ float g_b3[9*CHW];    // conv4 out (9)
__device__ float g_sum[4*16];
__device__ float g_sumsq[4*16];
__device__ float g_mean[4*16];
__device__ float g_istd[4*16];

struct Taps { int isl[9][3]; int msk[9][3]; float mult[9]; };

// ---------------- f32x2 helpers ----------------
__device__ __forceinline__ ull pack2(float v){
    ull r; asm("mov.b64 %0,{%1,%2};" : "=l"(r) : "f"(v), "f"(v)); return r;
}
__device__ __forceinline__ void fma2(ull &d, ull a, ull b){
    asm("fma.rn.f32x2 %0,%1,%2,%0;" : "+l"(d) : "l"(a), "l"(b));
}
__device__ __forceinline__ void unpack2(ull a, float &x, float &y){
    asm("mov.b64 {%0,%1},%2;" : "=f"(x), "=f"(y) : "l"(a));
}

// ---------------- fused conv stage ----------------
// MODE 0: raw input. MODE 1: relu((x-m)*istd). MODE 2: relu((x-m)*istd + skip).
// Block: 128 threads, each computes a 2x2 pixel patch x 16 output channels.
// Tile: 16(z) x 32(y). Grid: x = 32 spatial tiles, y = output slice.
// Epilogue: writes outputs + accumulates multiplicity-weighted sum/sumsq atomics.
template<int MODE>
__global__ __launch_bounds__(128) void conv_stage(
    const float* __restrict__ in, size_t in_stride,
    float* __restrict__ out,
    const float* __restrict__ w, const float* __restrict__ bias,
    const float* __restrict__ meanp, const float* __restrict__ istdp,
    const float* __restrict__ skip,
    float* __restrict__ stat_s, float* __restrict__ stat_q,
    Taps tp)
{
    __shared__ float s_w[16*9*16];      // [ci][k][co], mask-summed over kx
    __shared__ float s_in[16*18*34];    // [ci][r][c], transformed, halo'd

    const int osl = blockIdx.y;
    const int tzb = blockIdx.x >> 2, tyb = blockIdx.x & 3;
    const int tz0 = tzb*16, ty0 = tyb*32;
    const int tid = threadIdx.x;
    const int tz = tid >> 4, ty = tid & 15;

    ull acc[2][2][8];
#pragma unroll
    for (int a=0;a<2;a++)
#pragma unroll
    for (int b=0;b<2;b++)
#pragma unroll
    for (int t=0;t<8;t++) acc[a][b][t] = 0ull;

    for (int e=0; e<3; e++){
        const int isl = tp.isl[osl][e];
        if (isl < 0) continue;
        const int m = tp.msk[osl][e];
        __syncthreads();
        // weights (summed over kx taps sharing this input slice)
        for (int idx=tid; idx<2304; idx+=128){
            int co = idx & 15;
            int k  = (idx >> 4) % 9;
            int ci = idx / 144;
            int base = ((co*16+ci)*9 + k)*3;
            float wv = 0.f;
            if (m & 1) wv += w[base+0];
            if (m & 2) wv += w[base+1];
            if (m & 4) wv += w[base+2];
            s_w[idx] = wv;
        }
        // input tile (with fused elementwise transform)
        const float* ip = in + (size_t)isl*in_stride;
        for (int ci=0; ci<16; ci++){
            float mu=0.f, isd=0.f;
            if (MODE>0){ mu = meanp[ci]; isd = istdp[ci]; }
            const float* ipc = ip + ci*HW;
            const float* spc = (MODE==2) ? (skip + ci*HW) : ipc;
            for (int j=tid; j<612; j+=128){
                int r = j/34, c = j - r*34;
                int gz = tz0 + r - 1, gy = ty0 + c - 1;
                float vv = 0.f;
                if ((unsigned)gz < 128u && (unsigned)gy < 128u){
                    int px = gz*128 + gy;
                    float x = ipc[px];
                    if (MODE==0)      vv = x;
                    else if (MODE==1) vv = fmaxf((x-mu)*isd, 0.f);
                    else              vv = fmaxf((x-mu)*isd + spc[px], 0.f);
                }
                s_in[ci*612 + j] = vv;
            }
        }
        __syncthreads();
        // compute: 2x2 pixels x 16 co, f32x2-paired over co
        const float* sbase = s_in + (tz*2)*34 + ty*2;
#pragma unroll 1
        for (int ci=0; ci<16; ci++){
            const float* si = sbase + ci*612;
            float v[4][4];
#pragma unroll
            for (int rr=0; rr<4; rr++){
                float2 a = *reinterpret_cast<const float2*>(si + rr*34);
                float2 b = *reinterpret_cast<const float2*>(si + rr*34 + 2);
                v[rr][0]=a.x; v[rr][1]=a.y; v[rr][2]=b.x; v[rr][3]=b.y;
            }
            const ull* wp = reinterpret_cast<const ull*>(s_w + ci*144);
#pragma unroll
            for (int k=0; k<9; k++){
                const int kz = k/3, ky = k - kz*3;
                ull wv[8];
#pragma unroll
                for (int t=0;t<8;t++) wv[t] = wp[k*8+t];
#pragma unroll
                for (int pz=0; pz<2; pz++)
#pragma unroll
                for (int py=0; py<2; py++){
                    ull vp = pack2(v[pz+kz][py+ky]);
#pragma unroll
                    for (int t=0;t<8;t++) fma2(acc[pz][py][t], vp, wv[t]);
                }
            }
        }
    }

    // epilogue: bias, store, fused stats
    float bv[16];
#pragma unroll
    for (int co=0;co<16;co++) bv[co] = bias[co];

    float s[16], q[16];
#pragma unroll
    for (int co=0;co<16;co++){ s[co]=0.f; q[co]=0.f; }

    const int oz0 = tz0 + 2*tz, oy0 = ty0 + 2*ty;
    float* op = out + (size_t)osl*CHW;
#pragma unroll
    for (int pz=0; pz<2; pz++)
#pragma unroll
    for (int py=0; py<2; py++){
        const int pix = (oz0+pz)*128 + (oy0+py);
#pragma unroll
        for (int t=0;t<8;t++){
            float x,y; unpack2(acc[pz][py][t], x, y);
            float v0 = x + bv[2*t];
            float v1 = y + bv[2*t+1];
            op[(2*t)*HW   + pix] = v0;
            op[(2*t+1)*HW + pix] = v1;
            s[2*t]   += v0;  q[2*t]   += v0*v0;
            s[2*t+1] += v1;  q[2*t+1] += v1*v1;
        }
    }
#pragma unroll
    for (int co=0;co<16;co++){
#pragma unroll
        for (int o=16;o>0;o>>=1){
            s[co] += __shfl_xor_sync(0xffffffffu, s[co], o);
            q[co] += __shfl_xor_sync(0xffffffffu, q[co], o);
        }
    }
    if ((tid & 31) == 0){
        const float mlt = tp.mult[osl];
#pragma unroll
        for (int co=0;co<16;co++){
            atomicAdd(&stat_s[co], mlt*s[co]);
            atomicAdd(&stat_q[co], mlt*q[co]);
        }
    }
}

// ---------------- stats ----------------
__global__ void zero_stats(){
    int i = threadIdx.x;
    if (i < 64){ g_sum[i]=0.f; g_sumsq[i]=0.f; }
}

__global__ void fin_stats(int bank){
    int c = threadIdx.x;
    if (c < 16){
        double sd = (double)g_sum[bank*16+c];
        double qd = (double)g_sumsq[bank*16+c];
        double mean = sd / 2097152.0;
        double var  = qd / 2097152.0 - mean*mean;
        g_mean[bank*16+c] = (float)mean;
        g_istd[bank*16+c] = (float)(1.0/sqrt(var + 1e-5));
    }
}

// ---------------- fused final elementwise + forward projection ----------------
// final[sl] = relu( norm3(s3[sl]) + relu( norm1(s2[skm[sl]]) + V ) )
// out[c,0,z,u] = weighted slice sum at (z,y=u)
// out[c,1,z,u] = column sum over y of slice sel(u); u==0 sums only y=0..63
//   (reference fp32: x=+-3.9e-15 at uu=0, valid mask kills y in [64,127]).
__global__ __launch_bounds__(128) void forward_proj(
    const float* __restrict__ s3, const float* __restrict__ s2,
    const float* __restrict__ V, float* __restrict__ out)
{
    __shared__ float red[9][4];
    __shared__ float rs[9];
    const int c = blockIdx.x >> 7, z = blockIdx.x & 127;
    const int u = threadIdx.x;
    const int   skm[9]  = {0,1,2,2,2,2,2,3,4};
    const float mult[9] = {1.f,1.f,1.f,1.f,120.f,1.f,1.f,1.f,1.f};

    const float m1 = g_mean[16+c], i1 = g_istd[16+c];
    const float m3 = g_mean[48+c], i3 = g_istd[48+c];

    const int pix = z*128 + u;
    const float vb = V[c*HW + pix];

    float vals[9]; float s0 = 0.f;
#pragma unroll
    for (int sdx=0; sdx<9; sdx++){
        float t2 = s2[(size_t)(skm[sdx]*16 + c)*HW + pix];
        float sk = fmaxf((t2 - m1)*i1 + vb, 0.f);
        float t3 = s3[(size_t)(sdx*16 + c)*HW + pix];
        float fv = fmaxf((t3 - m3)*i3 + sk, 0.f);
        vals[sdx] = fv;
        s0 += mult[sdx]*fv;
    }
    out[(c*2+0)*HW + pix] = s0;

    const int lane = u & 31, wid = u >> 5;
#pragma unroll
    for (int sdx=0; sdx<9; sdx++){
        float v = vals[sdx];
#pragma unroll
        for (int o=16;o>0;o>>=1) v += __shfl_xor_sync(0xffffffffu, v, o);
        if (lane==0) red[sdx][wid]=v;
    }
    __syncthreads();
    if (u < 9) rs[u] = red[u][0]+red[u][1]+red[u][2]+red[u][3];
    __syncthreads();
    const int sl = (u<4) ? u : (u>123 ? u-119 : 4);
    float o1 = (u==0) ? (red[0][0]+red[0][1]) : rs[sl];
    out[(c*2+1)*HW + pix] = o1;
}

// ---------------- launch ----------------
extern "C" void kernel_launch(void* const* d_in, const int* in_sizes, int n_in,
                              void* d_out, int out_size)
{
    (void)in_sizes; (void)n_in; (void)out_size;
    const float* V    = (const float*)d_in[0];
    const float* w_a1 = (const float*)d_in[1];
    const float* b_a1 = (const float*)d_in[2];
    const float* w_a2 = (const float*)d_in[3];
    const float* b_a2 = (const float*)d_in[4];
    const float* w_b1 = (const float*)d_in[5];
    const float* b_b1 = (const float*)d_in[6];
    const float* w_b2 = (const float*)d_in[7];
    const float* b_b2 = (const float*)d_in[8];
    float* out = (float*)d_out;

    float *b1,*b2,*b3,*gsum,*gsq,*gmean,*gistd;
    cudaGetSymbolAddress((void**)&b1,    g_b1);
    cudaGetSymbolAddress((void**)&b2,    g_b2);
    cudaGetSymbolAddress((void**)&b3,    g_b3);
    cudaGetSymbolAddress((void**)&gsum,  g_sum);
    cudaGetSymbolAddress((void**)&gsq,   g_sumsq);
    cudaGetSymbolAddress((void**)&gmean, g_mean);
    cudaGetSymbolAddress((void**)&gistd, g_istd);

    // merged tap tables: (input slice, kx bitmask) per output slice
    Taps tA1 = {
        { {0,-1,-1},{0,-1,-1},{0,-1,-1} },
        { {6,0,0},{7,0,0},{3,0,0} },
        { 1.f,126.f,1.f }
    };
    Taps tA2 = {
        { {0,1,-1},{0,1,-1},{1,-1,-1},{1,2,-1},{1,2,-1} },
        { {2,4,0},{1,6,0},{7,0,0},{3,4,0},{1,2,0} },
        { 1.f,1.f,124.f,1.f,1.f }
    };
    Taps tB1 = {
        { {0,1,-1},{0,1,2},{1,2,-1},{2,-1,-1},{2,3,-1},{2,3,4},{3,4,-1} },
        { {2,4,0},{1,2,4},{1,6,0},{7,0,0},{3,4,0},{1,2,4},{1,2,0} },
        { 1.f,1.f,1.f,122.f,1.f,1.f,1.f }
    };
    Taps tB2 = {
        { {0,1,-1},{0,1,2},{1,2,3},{2,3,-1},{3,-1,-1},{3,4,-1},{3,4,5},{4,5,6},{5,6,-1} },
        { {2,4,0},{1,2,4},{1,2,4},{1,6,0},{7,0,0},{3,4,0},{1,2,4},{1,2,4},{1,2,0} },
        { 1.f,1.f,1.f,1.f,120.f,1.f,1.f,1.f,1.f }
    };

    zero_stats<<<1,64>>>();

    // A1: raw V (slice stride 0) -> b1 (3 slices), stats bank 0
    conv_stage<0><<<dim3(32,3),128>>>(V, 0, b1, w_a1, b_a1,
                                      nullptr, nullptr, nullptr,
                                      gsum+0, gsq+0, tA1);
    fin_stats<<<1,16>>>(0);

    // A2: norm_relu(b1, bank0) -> b2 (5), stats bank 1
    conv_stage<1><<<dim3(32,5),128>>>(b1, CHW, b2, w_a2, b_a2,
                                      gmean+0, gistd+0, nullptr,
                                      gsum+16, gsq+16, tA2);
    fin_stats<<<1,16>>>(1);

    // B1: relu(norm(b2, bank1) + V) -> b1 (7), stats bank 2
    conv_stage<2><<<dim3(32,7),128>>>(b2, CHW, b1, w_b1, b_b1,
                                      gmean+16, gistd+16, V,
                                      gsum+32, gsq+32, tB1);
    fin_stats<<<1,16>>>(2);

    // B2: norm_relu(b1, bank2) -> b3 (9), stats bank 3
    conv_stage<1><<<dim3(32,9),128>>>(b1, CHW, b3, w_b2, b_b2,
                                      gmean+32, gistd+32, nullptr,
                                      gsum+48, gsq+48, tB2);
    fin_stats<<<1,16>>>(3);

    // fused final norm+skip+relu + both projections
    forward_proj<<<16*128,128>>>(b3, b2, V, out);
}

// round 4
// speedup vs baseline: 1.2787x; 1.2787x over previous
#include <cuda_runtime.h>
#include <math.h>

#define HW   (128*128)
#define CHW  (16*HW)
typedef unsigned long long ull;

// ---------------- scratch ----------------
__device__ float g_b1[7*CHW];    // conv1 out (3) / conv3 out (7)
__device__ float g_b2[5*CHW];    // conv2 out (5) -- kept for final skip recompute
__device__ float g_b3[9*CHW];    // conv4 out (9)
__device__ float g_sum[4*16];
__device__ float g_sumsq[4*16];
__device__ float g_mean[4*16];
__device__ float g_istd[4*16];

struct Taps { int isl[9][3]; int msk[9][3]; float mult[9]; };

// ---------------- f32x2 helpers ----------------
__device__ __forceinline__ ull pack2(float v){
    ull r; asm("mov.b64 %0,{%1,%2};" : "=l"(r) : "f"(v), "f"(v)); return r;
}
__device__ __forceinline__ void fma2(ull &d, ull a, ull b){
    asm("fma.rn.f32x2 %0,%1,%2,%0;" : "+l"(d) : "l"(a), "l"(b));
}
__device__ __forceinline__ void unpack2(ull a, float &x, float &y){
    asm("mov.b64 {%0,%1},%2;" : "=f"(x), "=f"(y) : "l"(a));
}

// ---------------- fused conv stage ----------------
// MODE 0: raw input. MODE 1: relu((x-m)*istd). MODE 2: relu((x-m)*istd + skip).
// Block: 128 threads (16 z-rows x 8 y-groups), each thread 1x2 pixels x 16 co
// held as 16 f32x2 accumulators. Tile 16x16, grid x = 64 tiles, y = out slice.
template<int MODE>
__global__ __launch_bounds__(128) void conv_stage(
    const float* __restrict__ in, size_t in_stride,
    float* __restrict__ out,
    const float* __restrict__ w, const float* __restrict__ bias,
    const float* __restrict__ meanp, const float* __restrict__ istdp,
    const float* __restrict__ skip,
    float* __restrict__ stat_s, float* __restrict__ stat_q,
    Taps tp)
{
    __shared__ float s_w[16*9*16];      // [ci][k][co], mask-summed over kx (co pairs = ull)
    __shared__ float s_in[16*18*18];    // [ci][r][c]; c=0 corresponds to gy0-1

    const int osl = blockIdx.y;
    const int tile = blockIdx.x;
    const int tz0 = (tile >> 3) << 4;
    const int ty0 = (tile &  7) << 4;
    const int tid = threadIdx.x;
    const int tz  = tid >> 3;          // 0..15
    const int ty8 = tid & 7;           // 0..7 -> pixels y = 2*ty8, 2*ty8+1

    ull acc[2][8];
#pragma unroll
    for (int p=0;p<2;p++)
#pragma unroll
    for (int t=0;t<8;t++) acc[p][t] = 0ull;

    for (int e=0; e<3; e++){
        const int isl = tp.isl[osl][e];
        if (isl < 0) continue;
        const int m = tp.msk[osl][e];
        __syncthreads();
        // weights (summed over kx taps sharing this input slice)
        for (int idx=tid; idx<2304; idx+=128){
            int co = idx & 15;
            int k  = (idx >> 4) % 9;
            int ci = idx / 144;
            int base = ((co*16+ci)*9 + k)*3;
            float wv = 0.f;
            if (m & 1) wv += w[base+0];
            if (m & 2) wv += w[base+1];
            if (m & 4) wv += w[base+2];
            s_w[idx] = wv;
        }
        // input tile (fused elementwise transform), 16 ci x 18x18
        const float* ip = in + (size_t)isl*in_stride;
        for (int ci=0; ci<16; ci++){
            float mu=0.f, isd=0.f;
            if (MODE>0){ mu = meanp[ci]; isd = istdp[ci]; }
            const float* ipc = ip + ci*HW;
            const float* spc = (MODE==2) ? (skip + ci*HW) : ipc;
            for (int j=tid; j<324; j+=128){
                int r = j/18, c = j - r*18;
                int gz = tz0 + r - 1, gy = ty0 + c - 1;
                float vv = 0.f;
                if ((unsigned)gz < 128u && (unsigned)gy < 128u){
                    int px = gz*128 + gy;
                    float x = ipc[px];
                    if (MODE==0)      vv = x;
                    else if (MODE==1) vv = fmaxf((x-mu)*isd, 0.f);
                    else              vv = fmaxf((x-mu)*isd + spc[px], 0.f);
                }
                s_in[ci*324 + j] = vv;
            }
        }
        __syncthreads();

        // compute
        const float* sbase = s_in + tz*18 + ty8*2;   // aligned: halo at c=0
#pragma unroll 1
        for (int ci=0; ci<16; ci++){
            const float* si = sbase + ci*324;
            float v[3][4];
#pragma unroll
            for (int r=0; r<3; r++){
                float2 a = *reinterpret_cast<const float2*>(si + r*18);
                float2 b = *reinterpret_cast<const float2*>(si + r*18 + 2);
                v[r][0]=a.x; v[r][1]=a.y; v[r][2]=b.x; v[r][3]=b.y;
            }
            const ull* wp = reinterpret_cast<const ull*>(s_w + ci*144);
#pragma unroll
            for (int k=0; k<9; k++){
                const int kz = k/3, ky = k - kz*3;
                ull w0=wp[k*8+0], w1=wp[k*8+1], w2=wp[k*8+2], w3=wp[k*8+3];
                ull w4=wp[k*8+4], w5=wp[k*8+5], w6=wp[k*8+6], w7=wp[k*8+7];
                ull p0 = pack2(v[kz][ky]);
                ull p1 = pack2(v[kz][ky+1]);
                fma2(acc[0][0],p0,w0); fma2(acc[0][1],p0,w1);
                fma2(acc[0][2],p0,w2); fma2(acc[0][3],p0,w3);
                fma2(acc[0][4],p0,w4); fma2(acc[0][5],p0,w5);
                fma2(acc[0][6],p0,w6); fma2(acc[0][7],p0,w7);
                fma2(acc[1][0],p1,w0); fma2(acc[1][1],p1,w1);
                fma2(acc[1][2],p1,w2); fma2(acc[1][3],p1,w3);
                fma2(acc[1][4],p1,w4); fma2(acc[1][5],p1,w5);
                fma2(acc[1][6],p1,w6); fma2(acc[1][7],p1,w7);
            }
        }
    }

    // epilogue: bias, store, fused stats
    float bv[16];
#pragma unroll
    for (int co=0;co<16;co++) bv[co] = bias[co];

    float s[16], q[16];
#pragma unroll
    for (int co=0;co<16;co++){ s[co]=0.f; q[co]=0.f; }

    const int oz = tz0 + tz, oy = ty0 + 2*ty8;
    float* op = out + (size_t)osl*CHW;
#pragma unroll
    for (int p=0; p<2; p++){
        const int pix = oz*128 + oy + p;
#pragma unroll
        for (int t=0;t<8;t++){
            float x,y; unpack2(acc[p][t], x, y);
            float v0 = x + bv[2*t];
            float v1 = y + bv[2*t+1];
            op[(2*t)*HW   + pix] = v0;
            op[(2*t+1)*HW + pix] = v1;
            s[2*t]   += v0;  q[2*t]   += v0*v0;
            s[2*t+1] += v1;  q[2*t+1] += v1*v1;
        }
    }
#pragma unroll
    for (int co=0;co<16;co++){
#pragma unroll
        for (int o=16;o>0;o>>=1){
            s[co] += __shfl_xor_sync(0xffffffffu, s[co], o);
            q[co] += __shfl_xor_sync(0xffffffffu, q[co], o);
        }
    }
    if ((tid & 31) == 0){
        const float mlt = tp.mult[osl];
#pragma unroll
        for (int co=0;co<16;co++){
            atomicAdd(&stat_s[co], mlt*s[co]);
            atomicAdd(&stat_q[co], mlt*q[co]);
        }
    }
}

// ---------------- stats ----------------
__global__ void zero_stats(){
    int i = threadIdx.x;
    if (i < 64){ g_sum[i]=0.f; g_sumsq[i]=0.f; }
}

__global__ void fin_stats(int bank){
    int c = threadIdx.x;
    if (c < 16){
        double sd = (double)g_sum[bank*16+c];
        double qd = (double)g_sumsq[bank*16+c];
        double mean = sd / 2097152.0;
        double var  = qd / 2097152.0 - mean*mean;
        g_mean[bank*16+c] = (float)mean;
        g_istd[bank*16+c] = (float)(1.0/sqrt(var + 1e-5));
    }
}

// ---------------- fused final elementwise + forward projection ----------------
// final[sl] = relu( norm3(s3[sl]) + relu( norm1(s2[skm[sl]]) + V ) )
// out[c,0,z,u] = weighted slice sum at (z,y=u)
// out[c,1,z,u] = column sum over y of slice sel(u); u==0 sums only y=0..63
//   (reference fp32: x=+-3.9e-15 at uu=0, valid mask kills y in [64,127]).
__global__ __launch_bounds__(128) void forward_proj(
    const float* __restrict__ s3, const float* __restrict__ s2,
    const float* __restrict__ V, float* __restrict__ out)
{
    __shared__ float red[9][4];
    __shared__ float rs[9];
    const int c = blockIdx.x >> 7, z = blockIdx.x & 127;
    const int u = threadIdx.x;
    const int   skm[9]  = {0,1,2,2,2,2,2,3,4};
    const float mult[9] = {1.f,1.f,1.f,1.f,120.f,1.f,1.f,1.f,1.f};

    const float m1 = g_mean[16+c], i1 = g_istd[16+c];
    const float m3 = g_mean[48+c], i3 = g_istd[48+c];

    const int pix = z*128 + u;
    const float vb = V[c*HW + pix];

    float vals[9]; float s0 = 0.f;
#pragma unroll
    for (int sdx=0; sdx<9; sdx++){
        float t2 = s2[(size_t)(skm[sdx]*16 + c)*HW + pix];
        float sk = fmaxf((t2 - m1)*i1 + vb, 0.f);
        float t3 = s3[(size_t)(sdx*16 + c)*HW + pix];
        float fv = fmaxf((t3 - m3)*i3 + sk, 0.f);
        vals[sdx] = fv;
        s0 += mult[sdx]*fv;
    }
    out[(c*2+0)*HW + pix] = s0;

    const int lane = u & 31, wid = u >> 5;
#pragma unroll
    for (int sdx=0; sdx<9; sdx++){
        float v = vals[sdx];
#pragma unroll
        for (int o=16;o>0;o>>=1) v += __shfl_xor_sync(0xffffffffu, v, o);
        if (lane==0) red[sdx][wid]=v;
    }
    __syncthreads();
    if (u < 9) rs[u] = red[u][0]+red[u][1]+red[u][2]+red[u][3];
    __syncthreads();
    const int sl = (u<4) ? u : (u>123 ? u-119 : 4);
    float o1 = (u==0) ? (red[0][0]+red[0][1]) : rs[sl];
    out[(c*2+1)*HW + pix] = o1;
}

// ---------------- launch ----------------
extern "C" void kernel_launch(void* const* d_in, const int* in_sizes, int n_in,
                              void* d_out, int out_size)
{
    (void)in_sizes; (void)n_in; (void)out_size;
    const float* V    = (const float*)d_in[0];
    const float* w_a1 = (const float*)d_in[1];
    const float* b_a1 = (const float*)d_in[2];
    const float* w_a2 = (const float*)d_in[3];
    const float* b_a2 = (const float*)d_in[4];
    const float* w_b1 = (const float*)d_in[5];
    const float* b_b1 = (const float*)d_in[6];
    const float* w_b2 = (const float*)d_in[7];
    const float* b_b2 = (const float*)d_in[8];
    float* out = (float*)d_out;

    float *b1,*b2,*b3,*gsum,*gsq,*gmean,*gistd;
    cudaGetSymbolAddress((void**)&b1,    g_b1);
    cudaGetSymbolAddress((void**)&b2,    g_b2);
    cudaGetSymbolAddress((void**)&b3,    g_b3);
    cudaGetSymbolAddress((void**)&gsum,  g_sum);
    cudaGetSymbolAddress((void**)&gsq,   g_sumsq);
    cudaGetSymbolAddress((void**)&gmean, g_mean);
    cudaGetSymbolAddress((void**)&gistd, g_istd);

    // merged tap tables: (input slice, kx bitmask) per output slice
    Taps tA1 = {
        { {0,-1,-1},{0,-1,-1},{0,-1,-1} },
        { {6,0,0},{7,0,0},{3,0,0} },
        { 1.f,126.f,1.f }
    };
    Taps tA2 = {
        { {0,1,-1},{0,1,-1},{1,-1,-1},{1,2,-1},{1,2,-1} },
        { {2,4,0},{1,6,0},{7,0,0},{3,4,0},{1,2,0} },
        { 1.f,1.f,124.f,1.f,1.f }
    };
    Taps tB1 = {
        { {0,1,-1},{0,1,2},{1,2,-1},{2,-1,-1},{2,3,-1},{2,3,4},{3,4,-1} },
        { {2,4,0},{1,2,4},{1,6,0},{7,0,0},{3,4,0},{1,2,4},{1,2,0} },
        { 1.f,1.f,1.f,122.f,1.f,1.f,1.f }
    };
    Taps tB2 = {
        { {0,1,-1},{0,1,2},{1,2,3},{2,3,-1},{3,-1,-1},{3,4,-1},{3,4,5},{4,5,6},{5,6,-1} },
        { {2,4,0},{1,2,4},{1,2,4},{1,6,0},{7,0,0},{3,4,0},{1,2,4},{1,2,4},{1,2,0} },
        { 1.f,1.f,1.f,1.f,120.f,1.f,1.f,1.f,1.f }
    };

    zero_stats<<<1,64>>>();

    // A1: raw V (slice stride 0) -> b1 (3 slices), stats bank 0
    conv_stage<0><<<dim3(64,3),128>>>(V, 0, b1, w_a1, b_a1,
                                      nullptr, nullptr, nullptr,
                                      gsum+0, gsq+0, tA1);
    fin_stats<<<1,16>>>(0);

    // A2: norm_relu(b1, bank0) -> b2 (5), stats bank 1
    conv_stage<1><<<dim3(64,5),128>>>(b1, CHW, b2, w_a2, b_a2,
                                      gmean+0, gistd+0, nullptr,
                                      gsum+16, gsq+16, tA2);
    fin_stats<<<1,16>>>(1);

    // B1: relu(norm(b2, bank1) + V) -> b1 (7), stats bank 2
    conv_stage<2><<<dim3(64,7),128>>>(b2, CHW, b1, w_b1, b_b1,
                                      gmean+16, gistd+16, V,
                                      gsum+32, gsq+32, tB1);
    fin_stats<<<1,16>>>(2);

    // B2: norm_relu(b1, bank2) -> b3 (9), stats bank 3
    conv_stage<1><<<dim3(64,9),128>>>(b1, CHW, b3, w_b2, b_b2,
                                      gmean+32, gistd+32, nullptr,
                                      gsum+48, gsq+48, tB2);
    fin_stats<<<1,16>>>(3);

    // fused final norm+skip+relu + both projections
    forward_proj<<<16*128,128>>>(b3, b2, V, out);
}

// round 5
// speedup vs baseline: 1.6183x; 1.2656x over previous
#include <cuda_runtime.h>
#include <math.h>

#define HW   (128*128)
#define CHW  (16*HW)
typedef unsigned long long ull;

// ---------------- scratch ----------------
__device__ float g_b1[7*CHW];    // conv1 out (3) / conv3 out (7)
__device__ float g_b2[5*CHW];    // conv2 out (5) -- kept for final skip recompute
__device__ float g_b3[9*CHW];    // conv4 out (9)
__device__ float g_sum[4*16];
__device__ float g_sumsq[4*16];

struct Taps { int isl[9][3]; int msk[9][3]; float mult[9]; };

// ---------------- f32x2 helpers ----------------
__device__ __forceinline__ ull pack2(float v){
    ull r; asm("mov.b64 %0,{%1,%2};" : "=l"(r) : "f"(v), "f"(v)); return r;
}
__device__ __forceinline__ void fma2(ull &d, ull a, ull b){
    asm("fma.rn.f32x2 %0,%1,%2,%0;" : "+l"(d) : "l"(a), "l"(b));
}
__device__ __forceinline__ void unpack2(ull a, float &x, float &y){
    asm("mov.b64 {%0,%1},%2;" : "=f"(x), "=f"(y) : "l"(a));
}

// ---------------- fused conv stage ----------------
// MODE 0: raw input. MODE 1: relu(fma(x,a,b)) with a=istd,b=-mean*istd from raw
// sums (finalized inline). MODE 2: relu(fma(x,a,b) + skip).
// Block: 128 threads (16 z x 8 y-pairs), thread = 1x2 px x 16 co (16 f32x2 acc).
// Tile 16x16, grid x = 64 tiles, y = output slice.
template<int MODE>
__global__ __launch_bounds__(128) void conv_stage(
    const float* __restrict__ in, size_t in_stride,
    float* __restrict__ out,
    const float* __restrict__ w, const float* __restrict__ bias,
    const float* __restrict__ prev_s, const float* __restrict__ prev_q,
    const float* __restrict__ skip,
    float* __restrict__ stat_s, float* __restrict__ stat_q,
    Taps tp)
{
    __shared__ float s_w[16*9*16];      // [ci][k][co], mask-summed over kx
    __shared__ float s_in[16*18*18];    // [ci][r][c]
    __shared__ float s_a[16], s_b[16];
    __shared__ float s_red[4][32];

    const int osl = blockIdx.y;
    const int tile = blockIdx.x;
    const int tz0 = (tile >> 3) << 4;
    const int ty0 = (tile &  7) << 4;
    const int tid = threadIdx.x;
    const int tz  = tid >> 3;          // 0..15
    const int ty8 = tid & 7;           // 0..7 -> pixels y = 2*ty8, 2*ty8+1

    // inline finalize of previous stage's instance-norm stats
    if (MODE > 0 && tid < 16){
        double sd = (double)prev_s[tid];
        double qd = (double)prev_q[tid];
        double mean = sd / 2097152.0;
        double var  = qd / 2097152.0 - mean*mean;
        double isd  = 1.0 / sqrt(var + 1e-5);
        s_a[tid] = (float)isd;
        s_b[tid] = (float)(-mean*isd);
    }

    // precompute tile-load slots (3 per thread; slot2 only for tid<68)
    int pxs[3]; bool oks[3];
#pragma unroll
    for (int s3=0; s3<3; s3++){
        int j = tid + s3*128;
        int r = j/18, c = j - r*18;
        int gz = tz0 + r - 1, gy = ty0 + c - 1;
        oks[s3] = (j < 324) && ((unsigned)gz < 128u) && ((unsigned)gy < 128u);
        pxs[s3] = gz*128 + gy;
    }
    const bool has2 = tid < 68;

    ull acc[2][8];
#pragma unroll
    for (int p=0;p<2;p++)
#pragma unroll
    for (int t=0;t<8;t++) acc[p][t] = 0ull;

    for (int e=0; e<3; e++){
        const int isl = tp.isl[osl][e];
        if (isl < 0) continue;
        const int m = tp.msk[osl][e];
        __syncthreads();
        // weights (summed over kx taps sharing this input slice)
        for (int idx=tid; idx<2304; idx+=128){
            int co = idx & 15;
            int k  = (idx >> 4) % 9;
            int ci = idx / 144;
            int base = ((co*16+ci)*9 + k)*3;
            float wv = 0.f;
            if (m & 1) wv += w[base+0];
            if (m & 2) wv += w[base+1];
            if (m & 4) wv += w[base+2];
            s_w[idx] = wv;
        }
        // input tile (fused elementwise transform), 16 ci x 324
        const float* ip = in + (size_t)isl*in_stride;
#pragma unroll 1
        for (int ci=0; ci<16; ci++){
            float a=1.f, b=0.f;
            if (MODE>0){ a = s_a[ci]; b = s_b[ci]; }
            const float* ipc = ip + ci*HW;
            const float* spc = (MODE==2) ? (skip + ci*HW) : ipc;
            float* sic = s_in + ci*324;
#pragma unroll
            for (int s3=0; s3<3; s3++){
                if (s3==2 && !has2) break;
                float vv = 0.f;
                if (oks[s3]){
                    float x = ipc[pxs[s3]];
                    if (MODE==0)      vv = x;
                    else if (MODE==1) vv = fmaxf(fmaf(x,a,b), 0.f);
                    else              vv = fmaxf(fmaf(x,a,b) + spc[pxs[s3]], 0.f);
                }
                sic[tid + s3*128] = vv;
            }
        }
        __syncthreads();

        // compute
        const float* sbase = s_in + tz*18 + ty8*2;
#pragma unroll 1
        for (int ci=0; ci<16; ci++){
            const float* si = sbase + ci*324;
            ull p[3][4];
#pragma unroll
            for (int r=0; r<3; r++){
                float2 a2 = *reinterpret_cast<const float2*>(si + r*18);
                float2 b2 = *reinterpret_cast<const float2*>(si + r*18 + 2);
                p[r][0]=pack2(a2.x); p[r][1]=pack2(a2.y);
                p[r][2]=pack2(b2.x); p[r][3]=pack2(b2.y);
            }
            const float* wbase = s_w + ci*144;
#pragma unroll
            for (int k=0; k<9; k++){
                const int kz = k/3, ky = k - kz*3;
                const ulonglong2* wq = reinterpret_cast<const ulonglong2*>(wbase + k*16);
                ulonglong2 wa = wq[0], wb = wq[1];
                ull p0 = p[kz][ky], p1 = p[kz][ky+1];
                fma2(acc[0][0],p0,wa.x); fma2(acc[0][1],p0,wa.y);
                fma2(acc[0][2],p0,wb.x); fma2(acc[0][3],p0,wb.y);
                fma2(acc[1][0],p1,wa.x); fma2(acc[1][1],p1,wa.y);
                fma2(acc[1][2],p1,wb.x); fma2(acc[1][3],p1,wb.y);
                wa = wq[2]; wb = wq[3];
                fma2(acc[0][4],p0,wa.x); fma2(acc[0][5],p0,wa.y);
                fma2(acc[0][6],p0,wb.x); fma2(acc[0][7],p0,wb.y);
                fma2(acc[1][4],p1,wa.x); fma2(acc[1][5],p1,wa.y);
                fma2(acc[1][6],p1,wb.x); fma2(acc[1][7],p1,wb.y);
            }
        }
    }

    // epilogue: bias, store, fused stats
    float bv[16];
#pragma unroll
    for (int co=0;co<16;co++) bv[co] = bias[co];

    float s[16], q[16];
#pragma unroll
    for (int co=0;co<16;co++){ s[co]=0.f; q[co]=0.f; }

    const int oz = tz0 + tz, oy = ty0 + 2*ty8;
    float* op = out + (size_t)osl*CHW;
#pragma unroll
    for (int p=0; p<2; p++){
        const int pix = oz*128 + oy + p;
#pragma unroll
        for (int t=0;t<8;t++){
            float x,y; unpack2(acc[p][t], x, y);
            float v0 = x + bv[2*t];
            float v1 = y + bv[2*t+1];
            op[(2*t)*HW   + pix] = v0;
            op[(2*t+1)*HW + pix] = v1;
            s[2*t]   += v0;  q[2*t]   += v0*v0;
            s[2*t+1] += v1;  q[2*t+1] += v1*v1;
        }
    }
#pragma unroll
    for (int co=0;co<16;co++){
#pragma unroll
        for (int o=16;o>0;o>>=1){
            s[co] += __shfl_xor_sync(0xffffffffu, s[co], o);
            q[co] += __shfl_xor_sync(0xffffffffu, q[co], o);
        }
    }
    __syncthreads();
    if ((tid & 31) == 0){
        const int wd = tid >> 5;
#pragma unroll
        for (int co=0;co<16;co++){
            s_red[wd][co]    = s[co];
            s_red[wd][16+co] = q[co];
        }
    }
    __syncthreads();
    if (tid < 32){
        float t4 = s_red[0][tid] + s_red[1][tid] + s_red[2][tid] + s_red[3][tid];
        t4 *= tp.mult[osl];
        if (tid < 16) atomicAdd(&stat_s[tid], t4);
        else          atomicAdd(&stat_q[tid-16], t4);
    }
}

// ---------------- stats zero ----------------
__global__ void zero_stats(){
    int i = threadIdx.x;
    if (i < 64){ g_sum[i]=0.f; g_sumsq[i]=0.f; }
}

// ---------------- fused final elementwise + forward projection ----------------
// final[sl] = relu( norm3(s3[sl]) + relu( norm1(s2[skm[sl]]) + V ) )
// out[c,0,z,u] = weighted slice sum at (z,y=u)
// out[c,1,z,u] = column sum over y of slice sel(u); u==0 sums only y=0..63
//   (reference fp32: x=+-3.9e-15 at uu=0, valid mask kills y in [64,127]).
__global__ __launch_bounds__(128) void forward_proj(
    const float* __restrict__ s3, const float* __restrict__ s2,
    const float* __restrict__ V, float* __restrict__ out)
{
    __shared__ float red[9][4];
    __shared__ float rs[9];
    const int c = blockIdx.x >> 7, z = blockIdx.x & 127;
    const int u = threadIdx.x;
    const int   skm[9]  = {0,1,2,2,2,2,2,3,4};
    const float mult[9] = {1.f,1.f,1.f,1.f,120.f,1.f,1.f,1.f,1.f};

    // inline stats finalize: bank1 (A2 output) and bank3 (B2 output)
    double sd1 = (double)g_sum[16+c], qd1 = (double)g_sumsq[16+c];
    double me1 = sd1/2097152.0;
    double i1d = 1.0/sqrt(qd1/2097152.0 - me1*me1 + 1e-5);
    const float i1 = (float)i1d, b1c = (float)(-me1*i1d);
    double sd3 = (double)g_sum[48+c], qd3 = (double)g_sumsq[48+c];
    double me3 = sd3/2097152.0;
    double i3d = 1.0/sqrt(qd3/2097152.0 - me3*me3 + 1e-5);
    const float i3 = (float)i3d, b3c = (float)(-me3*i3d);

    const int pix = z*128 + u;
    const float vb = V[c*HW + pix];

    float vals[9]; float s0 = 0.f;
#pragma unroll
    for (int sdx=0; sdx<9; sdx++){
        float t2 = s2[(size_t)(skm[sdx]*16 + c)*HW + pix];
        float sk = fmaxf(fmaf(t2, i1, b1c) + vb, 0.f);
        float t3 = s3[(size_t)(sdx*16 + c)*HW + pix];
        float fv = fmaxf(fmaf(t3, i3, b3c) + sk, 0.f);
        vals[sdx] = fv;
        s0 += mult[sdx]*fv;
    }
    out[(c*2+0)*HW + pix] = s0;

    const int lane = u & 31, wid = u >> 5;
#pragma unroll
    for (int sdx=0; sdx<9; sdx++){
        float v = vals[sdx];
#pragma unroll
        for (int o=16;o>0;o>>=1) v += __shfl_xor_sync(0xffffffffu, v, o);
        if (lane==0) red[sdx][wid]=v;
    }
    __syncthreads();
    if (u < 9) rs[u] = red[u][0]+red[u][1]+red[u][2]+red[u][3];
    __syncthreads();
    const int sl = (u<4) ? u : (u>123 ? u-119 : 4);
    float o1 = (u==0) ? (red[0][0]+red[0][1]) : rs[sl];
    out[(c*2+1)*HW + pix] = o1;
}

// ---------------- launch ----------------
extern "C" void kernel_launch(void* const* d_in, const int* in_sizes, int n_in,
                              void* d_out, int out_size)
{
    (void)in_sizes; (void)n_in; (void)out_size;
    const float* V    = (const float*)d_in[0];
    const float* w_a1 = (const float*)d_in[1];
    const float* b_a1 = (const float*)d_in[2];
    const float* w_a2 = (const float*)d_in[3];
    const float* b_a2 = (const float*)d_in[4];
    const float* w_b1 = (const float*)d_in[5];
    const float* b_b1 = (const float*)d_in[6];
    const float* w_b2 = (const float*)d_in[7];
    const float* b_b2 = (const float*)d_in[8];
    float* out = (float*)d_out;

    float *b1,*b2,*b3,*gsum,*gsq;
    cudaGetSymbolAddress((void**)&b1,    g_b1);
    cudaGetSymbolAddress((void**)&b2,    g_b2);
    cudaGetSymbolAddress((void**)&b3,    g_b3);
    cudaGetSymbolAddress((void**)&gsum,  g_sum);
    cudaGetSymbolAddress((void**)&gsq,   g_sumsq);

    // merged tap tables: (input slice, kx bitmask) per output slice
    Taps tA1 = {
        { {0,-1,-1},{0,-1,-1},{0,-1,-1} },
        { {6,0,0},{7,0,0},{3,0,0} },
        { 1.f,126.f,1.f }
    };
    Taps tA2 = {
        { {0,1,-1},{0,1,-1},{1,-1,-1},{1,2,-1},{1,2,-1} },
        { {2,4,0},{1,6,0},{7,0,0},{3,4,0},{1,2,0} },
        { 1.f,1.f,124.f,1.f,1.f }
    };
    Taps tB1 = {
        { {0,1,-1},{0,1,2},{1,2,-1},{2,-1,-1},{2,3,-1},{2,3,4},{3,4,-1} },
        { {2,4,0},{1,2,4},{1,6,0},{7,0,0},{3,4,0},{1,2,4},{1,2,0} },
        { 1.f,1.f,1.f,122.f,1.f,1.f,1.f }
    };
    Taps tB2 = {
        { {0,1,-1},{0,1,2},{1,2,3},{2,3,-1},{3,-1,-1},{3,4,-1},{3,4,5},{4,5,6},{5,6,-1} },
        { {2,4,0},{1,2,4},{1,2,4},{1,6,0},{7,0,0},{3,4,0},{1,2,4},{1,2,4},{1,2,0} },
        { 1.f,1.f,1.f,1.f,120.f,1.f,1.f,1.f,1.f }
    };

    zero_stats<<<1,64>>>();

    // A1: raw V (slice stride 0) -> b1 (3 slices), stats bank 0
    conv_stage<0><<<dim3(64,3),128>>>(V, 0, b1, w_a1, b_a1,
                                      nullptr, nullptr, nullptr,
                                      gsum+0, gsq+0, tA1);

    // A2: norm_relu(b1, bank0) -> b2 (5), stats bank 1
    conv_stage<1><<<dim3(64,5),128>>>(b1, CHW, b2, w_a2, b_a2,
                                      gsum+0, gsq+0, nullptr,
                                      gsum+16, gsq+16, tA2);

    // B1: relu(norm(b2, bank1) + V) -> b1 (7), stats bank 2
    conv_stage<2><<<dim3(64,7),128>>>(b2, CHW, b1, w_b1, b_b1,
                                      gsum+16, gsq+16, V,
                                      gsum+32, gsq+32, tB1);

    // B2: norm_relu(b1, bank2) -> b3 (9), stats bank 3
    conv_stage<1><<<dim3(64,9),128>>>(b1, CHW, b3, w_b2, b_b2,
                                      gsum+32, gsq+32, nullptr,
                                      gsum+48, gsq+48, tB2);

    // fused final norm+skip+relu + both projections (bank1+bank3 inline)
    forward_proj<<<16*128,128>>>(b3, b2, V, out);
}